// round 17
// baseline (speedup 1.0000x reference)
#include <cuda_runtime.h>
#include <cuda_fp16.h>
#include <cstdint>

// Problem constants
#define IN_F     256
#define OUT_F    256
#define BATCH    512
#define NSEG     16
#define NT       49
#define KDIM     (IN_F * NT)        // 12544 (native K, no padding)

#define I_SPLIT  37                 // grid = 4 * 37 = 148 CTAs = #SMs
#define M_TILE   128

// Static device scratch
__device__ __half g_wh[(size_t)OUT_F * KDIM];               // fp16 weights, native layout, 6.4 MB
__device__ float  g_part[(size_t)I_SPLIT * BATCH * OUT_F];  // partials [split][b][o], 19.4 MB

// ---------------------------------------------------------------------------
// helpers
// ---------------------------------------------------------------------------
__device__ __forceinline__ uint32_t smem_u32(const void* p) {
    uint32_t a;
    asm("{ .reg .u64 t; cvta.to.shared.u64 t, %1; cvt.u32.u64 %0, t; }" : "=r"(a) : "l"(p));
    return a;
}
__device__ __forceinline__ void ldsm_x4(uint32_t* r, uint32_t addr) {
    asm volatile("ldmatrix.sync.aligned.m8n8.x4.shared.b16 {%0,%1,%2,%3}, [%4];"
                 : "=r"(r[0]), "=r"(r[1]), "=r"(r[2]), "=r"(r[3]) : "r"(addr));
}
__device__ __forceinline__ void mma16816(float* c, const uint32_t* a,
                                         uint32_t b0, uint32_t b1) {
    asm volatile(
        "mma.sync.aligned.m16n8k16.row.col.f32.f16.f16.f32 "
        "{%0,%1,%2,%3}, {%4,%5,%6,%7}, {%8,%9}, {%0,%1,%2,%3};"
        : "+f"(c[0]), "+f"(c[1]), "+f"(c[2]), "+f"(c[3])
        : "r"(a[0]), "r"(a[1]), "r"(a[2]), "r"(a[3]), "r"(b0), "r"(b1));
}
__device__ __forceinline__ uint32_t sw128(uint32_t off) {
    return off ^ ((off >> 3) & 0x70);
}
__device__ __forceinline__ void cp_async16(uint32_t dst, const void* src) {
    asm volatile("cp.async.cg.shared.global [%0], [%1], 16;"
                 :: "r"(dst), "l"(src) : "memory");
}

// ---------------------------------------------------------------------------
// Kernel 1: fp32 -> fp16 convert, layout preserved.
// ---------------------------------------------------------------------------
__global__ __launch_bounds__(256) void convert_w(const float* __restrict__ w) {
    const int idx = blockIdx.x * 256 + threadIdx.x;       // 0..802815
    float4 v = __ldg((const float4*)w + idx);
    uint32_t u0 = (uint32_t)__half_as_ushort(__float2half_rn(v.x))
                | ((uint32_t)__half_as_ushort(__float2half_rn(v.y)) << 16);
    uint32_t u1 = (uint32_t)__half_as_ushort(__float2half_rn(v.z))
                | ((uint32_t)__half_as_ushort(__float2half_rn(v.w)) << 16);
    *(uint2*)(g_wh + (size_t)idx * 4) = make_uint2(u0, u1);
}

// ---------------------------------------------------------------------------
// Kernel 2: mma.sync GEMM over NATIVE K, triple-buffered cp.async pipeline.
// Grid (4, 37) = 148 CTAs = #SMs. 512 threads = 4 M-warps x 4 N-warps (m32xn64).
// D[128,256] += A[128,K] * B[256,K]^T, K split at 16-half chunk granularity.
// ---------------------------------------------------------------------------
#define A_STRIDE 16384
#define B_BASE   49152
#define B_STRIDE 32768
#define SM_TOTAL 147456             // 48KB A + 96KB B

__global__ __launch_bounds__(512, 1) void pp_gemm(const float* __restrict__ x) {
    extern __shared__ char smem[];
    const uint32_t sb = smem_u32(smem);

    const int tid  = threadIdx.x;
    const int lane = tid & 31;
    const int wid  = tid >> 5;
    const int wm   = wid & 3;        // 4 M-warps x 32 rows
    const int wn   = wid >> 2;       // 4 N-warps x 64 cols
    const int bt0  = blockIdx.x * M_TILE;
    const int split = blockIdx.y;

    // chunk range: splits 0..6 -> 22 chunks, 7..36 -> 21 (total 784)
    const int nch = (split < 7) ? 22 : 21;
    const int c0  = (split < 7) ? split * 22 : 154 + (split - 7) * 21;

    // B slab copy: 2 threads per o-row, 16B per cp.async.
    auto cpB = [&](int cc, int nk, uint32_t boff) {
        const int o = tid >> 1;
        const __half* src = g_wh + (size_t)o * KDIM + cc * 16;
#pragma unroll 4
        for (int p = 0; p < nk; p++) {
            const int part = (tid & 1) + 2 * p;
            const uint32_t off = o * 128 + part * 16;
            cp_async16(sb + boff + sw128(off), src + part * 8);
        }
    };
    // A fill for k-range [k0, k0 + nk*16): zero row, write in-range nonzeros.
    auto fillA = [&](int k0, int nk, uint32_t aoff) {
        if (tid < M_TILE) {
            const uint4 z = make_uint4(0, 0, 0, 0);
#pragma unroll
            for (int q = 0; q < 8; q++)
                *(uint4*)(smem + aoff + tid * 128 + q * 16) = z;

            const int kend = k0 + nk * 16;
            const int i_lo = k0 / NT;
            const int i_hi = (kend - 1) / NT;
            for (int i = i_lo; i <= i_hi; i++) {
                const float xv = __ldg(x + (size_t)(bt0 + tid) * IN_F + i);
                int s = (int)((xv + 1.0f) * 0.5f * (float)NSEG);
                s = min(max(s, 0), NSEG - 1);
                const float xmin = (float)s * (2.0f / (float)NSEG) - 1.0f;
                const float xi   = (xv - xmin) * (float)NSEG - 1.0f;
                const float d0 = xi + 1.0f, d1 = xi + 0.5f, d2 = xi - 0.5f, d3 = xi - 1.0f;
                unsigned short h[4];
                h[0] = __half_as_ushort(__float2half_rn(d1 * d2 * d3 * (-1.0f / 1.5f)));
                h[1] = __half_as_ushort(__float2half_rn(d0 * d2 * d3 * ( 1.0f / 0.75f)));
                h[2] = __half_as_ushort(__float2half_rn(d0 * d1 * d3 * (-1.0f / 0.75f)));
                h[3] = __half_as_ushort(__float2half_rn(d0 * d1 * d2 * ( 1.0f / 1.5f)));
                const int kbase = i * NT + 3 * s;
#pragma unroll
                for (int j = 0; j < 4; j++) {
                    const int k = kbase + j;
                    if (k >= k0 && k < kend) {
                        const uint32_t off = tid * 128 + (k - k0) * 2;
                        *(unsigned short*)(smem + aoff + sw128(off)) = h[j];
                    }
                }
            }
        }
    };

    float acc[2][8][4];
#pragma unroll
    for (int mt = 0; mt < 2; mt++)
#pragma unroll
        for (int nt = 0; nt < 8; nt++)
#pragma unroll
            for (int q = 0; q < 4; q++) acc[mt][nt][q] = 0.f;

    // ldmatrix lane mappings / bases
    const int a_lr = lane & 15;
    const int a_lc = (lane >> 4) << 4;
    const int b_r8 = lane & 7;
    const int b_radd = (lane >> 4) << 3;
    const int b_cadd = ((lane >> 3) & 1) << 4;
    const uint32_t a_base = (wm * 32 + a_lr) * 128 + a_lc;
    const uint32_t b_base = (wn * 64 + b_radd + b_r8) * 128 + b_cadd;

    auto mma_step = [&](uint32_t Ab, uint32_t Bb, uint32_t kcol) {
        uint32_t a[2][4];
#pragma unroll
        for (int mt = 0; mt < 2; mt++)
            ldsm_x4(a[mt], Ab + sw128(a_base + mt * 16 * 128 + kcol));
#pragma unroll
        for (int g = 0; g < 4; g++) {
            uint32_t b[4];
            ldsm_x4(b, Bb + sw128(b_base + g * 16 * 128 + kcol));
#pragma unroll
            for (int mt = 0; mt < 2; mt++) {
                mma16816(acc[mt][2 * g],     a[mt], b[0], b[1]);
                mma16816(acc[mt][2 * g + 1], a[mt], b[2], b[3]);
            }
        }
    };

    // prologue: issue slabs 0 and 1 (groups g0, g1)
    cpB(c0, 4, B_BASE);
    fillA(c0 * 16, 4, 0);
    asm volatile("cp.async.commit_group;" ::: "memory");
    cpB(c0 + 4, 4, B_BASE + B_STRIDE);
    fillA((c0 + 4) * 16, 4, A_STRIDE);
    asm volatile("cp.async.commit_group;" ::: "memory");

    // 5 full slabs (nk = 4, unrolled)
#pragma unroll 1
    for (int sl = 0; sl < 5; sl++) {
        asm volatile("cp.async.wait_group 1;" ::: "memory");
        __syncthreads();

        // issue slab sl+2 into buffer (sl+2)%3 (last read at iter sl-1)
        if (sl + 2 <= 5) {
            const int cc2 = c0 + 4 * (sl + 2);
            const int nk2 = (sl + 2 < 5) ? 4 : (nch - 20);
            const int bi  = (sl + 2) % 3;
            cpB(cc2, nk2, B_BASE + bi * B_STRIDE);
            fillA(cc2 * 16, nk2, bi * A_STRIDE);
        }
        asm volatile("cp.async.commit_group;" ::: "memory");

        const int cb = sl % 3;
        const uint32_t Ab = sb + cb * A_STRIDE;
        const uint32_t Bb = sb + B_BASE + cb * B_STRIDE;
#pragma unroll
        for (int kk = 0; kk < 4; kk++)
            mma_step(Ab, Bb, kk * 32);
    }

    // tail slab 5 (1 or 2 chunks), buffer 5%3 = 2
    asm volatile("cp.async.wait_group 0;" ::: "memory");
    __syncthreads();
    {
        const uint32_t Ab = sb + 2 * A_STRIDE;
        const uint32_t Bb = sb + B_BASE + 2 * B_STRIDE;
        const int nk = nch - 20;
        mma_step(Ab, Bb, 0);
        if (nk == 2) mma_step(Ab, Bb, 32);
    }

    // epilogue
    {
        float* dst = g_part + (size_t)split * (BATCH * OUT_F);
        const int cb = wn * 64 + (lane & 3) * 2;
#pragma unroll
        for (int mt = 0; mt < 2; mt++) {
            const int r0 = bt0 + wm * 32 + mt * 16 + (lane >> 2);
#pragma unroll
            for (int nt = 0; nt < 8; nt++) {
                const int c = cb + nt * 8;
                *(float2*)(dst + (size_t)r0 * OUT_F + c) =
                    make_float2(acc[mt][nt][0], acc[mt][nt][1]);
                *(float2*)(dst + (size_t)(r0 + 8) * OUT_F + c) =
                    make_float2(acc[mt][nt][2], acc[mt][nt][3]);
            }
        }
    }
}

// ---------------------------------------------------------------------------
// Kernel 3: reduce the 37 i-split partials (fixed-order tree). Grid 512 x 512thr.
// ---------------------------------------------------------------------------
__global__ __launch_bounds__(512) void reduce_kernel(float* __restrict__ out) {
    __shared__ float4 sm[512];
    const int tid = threadIdx.x;
    const int o4  = blockIdx.x * 64 + (tid & 63);
    const int kg  = tid >> 6;

    const int start = (kg < 5) ? kg * 5 : 25 + (kg - 5) * 4;
    const int cnt   = (kg < 5) ? 5 : 4;

    const float4* p = (const float4*)g_part + o4;
    float4 s = make_float4(0.f, 0.f, 0.f, 0.f);
#pragma unroll
    for (int k = 0; k < 5; k++) {
        if (k >= cnt) break;
        float4 v = __ldg(p + (size_t)(start + k) * (BATCH * OUT_F / 4));
        s.x += v.x; s.y += v.y; s.z += v.z; s.w += v.w;
    }
    sm[tid] = s;
    __syncthreads();

    if (kg < 2) {
        float4 a = sm[tid], b = sm[tid + 128], c = sm[tid + 256], d = sm[tid + 384];
        float4 r;
        r.x = ((a.x + b.x) + c.x) + d.x;
        r.y = ((a.y + b.y) + c.y) + d.y;
        r.z = ((a.z + b.z) + c.z) + d.z;
        r.w = ((a.w + b.w) + c.w) + d.w;
        sm[tid] = r;
    }
    __syncthreads();
    if (kg == 0) {
        float4 a = sm[tid], b = sm[tid + 64];
        float4 r;
        r.x = a.x + b.x; r.y = a.y + b.y; r.z = a.z + b.z; r.w = a.w + b.w;
        ((float4*)out)[o4] = r;
    }
}

// ---------------------------------------------------------------------------
extern "C" void kernel_launch(void* const* d_in, const int* in_sizes, int n_in,
                              void* d_out, int out_size) {
    const float* x = (const float*)d_in[0];   // [512, 256] f32
    const float* w = (const float*)d_in[1];   // [256, 256, 49] f32
    float* out = (float*)d_out;               // [512, 256] f32
    (void)in_sizes; (void)n_in; (void)out_size;

    // 1) fp32 -> fp16 convert (layout preserved)
    convert_w<<<3136, 256>>>(w);

    // 2) HMMA GEMM over native K into split-K partials
    cudaFuncSetAttribute(pp_gemm, cudaFuncAttributeMaxDynamicSharedMemorySize, SM_TOTAL);
    {
        dim3 grid(BATCH / M_TILE, I_SPLIT);   // (4, 37) = 148 CTAs
        pp_gemm<<<grid, 512, SM_TOTAL>>>(x);
    }

    // 3) reduce partials
    reduce_kernel<<<512, 512>>>(out);
}